// round 14
// baseline (speedup 1.0000x reference)
#include <cuda_runtime.h>
#include <cuda_fp16.h>
#include <cstdint>

#define B_TOT 4096
#define DIN   2048
#define DOUT  2048
// per core: G[r=8][o=512][x=512][s=8], offset = r*2097152 + o*4096 + x*8 + s

__device__ float g_Ghat[4][8][4096];
__device__ float g_S[4][B_TOT][64];
__device__ float g_env[4][B_TOT][64];
// fp16 copy of G, fragment-interleaved:
// g_Gh[((core*8+r)*512+o)*4096 + grp*16 + p], grp = 16-float group in row,
// p = (s>>1)*4 + (x&1)*2 + (s&1)  -> thread tg reads halfs p=4tg..4tg+3
__device__ __half g_Gh[4u * 8u * 512u * 4096u];

// ---------------------------------------------------------------------------
// Kernel 0: zero g_Ghat (needed because k_prep accumulates via atomicAdd)
// ---------------------------------------------------------------------------
__global__ void k_zero()
{
    ((float*)g_Ghat)[blockIdx.x * 256 + threadIdx.x] = 0.f;   // grid 512
}

// ---------------------------------------------------------------------------
// Kernel 1 (fused): convert G -> fp16 interleaved AND reduce Ghat over o.
// grid 512 = core(4) x r(8) x ochunk(16); block 256; thread t owns 16-float
// group t of each row; loops 32 o's, atomicAdd partial Ghat at the end.
// ---------------------------------------------------------------------------
__global__ void k_prep(const float* __restrict__ c0, const float* __restrict__ c1,
                       const float* __restrict__ c2, const float* __restrict__ c3)
{
    int bid = blockIdx.x;
    int oc = bid & 15, r = (bid >> 4) & 7, core = bid >> 7;
    const float* G = (core == 0) ? c0 : (core == 1) ? c1 : (core == 2) ? c2 : c3;
    int t = threadIdx.x;

    const float* src = G + ((size_t)r * 512 + oc * 32) * 4096 + t * 16;
    __half* dst = g_Gh + ((size_t)(core * 8 + r) * 512 + oc * 32) * 4096 + t * 16;

    float acc[16];
#pragma unroll
    for (int i = 0; i < 16; i++) acc[i] = 0.f;

    for (int oi = 0; oi < 32; oi++) {
        float f[16];
        const float4* s4 = (const float4*)(src + (size_t)oi * 4096);
#pragma unroll
        for (int i = 0; i < 4; i++) {
            float4 v = s4[i];
            f[i * 4 + 0] = v.x; f[i * 4 + 1] = v.y; f[i * 4 + 2] = v.z; f[i * 4 + 3] = v.w;
        }
#pragma unroll
        for (int i = 0; i < 16; i++) acc[i] += f[i];
        __half2 h[8];
#pragma unroll
        for (int s2 = 0; s2 < 4; s2++) {
            h[2 * s2]     = __floats2half2_rn(f[2 * s2],     f[2 * s2 + 1]);     // x even
            h[2 * s2 + 1] = __floats2half2_rn(f[8 + 2 * s2], f[8 + 2 * s2 + 1]); // x odd
        }
        uint4* d4 = (uint4*)(dst + (size_t)oi * 4096);
        const uint32_t* hu = (const uint32_t*)h;
        d4[0] = make_uint4(hu[0], hu[1], hu[2], hu[3]);
        d4[1] = make_uint4(hu[4], hu[5], hu[6], hu[7]);
    }
    float* gh = &g_Ghat[core][r][t * 16];
#pragma unroll
    for (int i = 0; i < 16; i++) atomicAdd(gh + i, acc[i]);
}

// ---------------------------------------------------------------------------
// Kernel 2: S[core][b][r,s] = sum_x Ghat[core][r][x,s] * X[b][core*512+x]
// ---------------------------------------------------------------------------
__global__ void k_S(const float* __restrict__ X)
{
    __shared__ float xs[4][DIN];
    int t = threadIdx.x, b0 = blockIdx.x * 4;
#pragma unroll
    for (int it = 0; it < 32; it++) {
        int i = t + it * 256;
        xs[i >> 11][i & 2047] = X[(size_t)(b0 + (i >> 11)) * DIN + (i & 2047)];
    }
    __syncthreads();
    int core = t >> 6, rs = t & 63, r = rs >> 3, s = rs & 7;
    const float* gh = g_Ghat[core][r];
    const int xo = core * 512;
    float a0 = 0.f, a1 = 0.f, a2 = 0.f, a3 = 0.f;
#pragma unroll 8
    for (int x = 0; x < 512; x++) {
        float ghv = gh[x * 8 + s];
        a0 += ghv * xs[0][xo + x];
        a1 += ghv * xs[1][xo + x];
        a2 += ghv * xs[2][xo + x];
        a3 += ghv * xs[3][xo + x];
    }
    g_S[core][b0 + 0][rs] = a0;
    g_S[core][b0 + 1][rs] = a1;
    g_S[core][b0 + 2][rs] = a2;
    g_S[core][b0 + 3][rs] = a3;
}

// ---------------------------------------------------------------------------
// Kernel 3: chain products -> env
// ---------------------------------------------------------------------------
__global__ void k_chain()
{
    __shared__ float Sm[4][4][64];
    __shared__ float P2s[4][64], P3s[4][64], Q1s[4][64], Q0s[4][64];
    int t = threadIdx.x, bsub = t >> 6, rs = t & 63, r = rs >> 3, s = rs & 7;
    int b = blockIdx.x * 4 + bsub;
#pragma unroll
    for (int c = 0; c < 4; c++) Sm[bsub][c][rs] = g_S[c][b][rs];
    __syncthreads();
    float p2 = 0.f, q1 = 0.f;
#pragma unroll
    for (int p = 0; p < 8; p++) {
        p2 += Sm[bsub][0][r * 8 + p] * Sm[bsub][1][p * 8 + s];
        q1 += Sm[bsub][2][r * 8 + p] * Sm[bsub][3][p * 8 + s];
    }
    P2s[bsub][rs] = p2; Q1s[bsub][rs] = q1;
    __syncthreads();
    float p3 = 0.f, q0 = 0.f;
#pragma unroll
    for (int p = 0; p < 8; p++) {
        p3 += P2s[bsub][r * 8 + p] * Sm[bsub][2][p * 8 + s];
        q0 += Sm[bsub][1][r * 8 + p] * Q1s[bsub][p * 8 + s];
    }
    P3s[bsub][rs] = p3; Q0s[bsub][rs] = q0;
    __syncthreads();
    float e1 = 0.f, e2 = 0.f;
#pragma unroll
    for (int p = 0; p < 8; p++) {
        e1 += Q1s[bsub][s * 8 + p] * Sm[bsub][0][p * 8 + r];
        e2 += Sm[bsub][3][s * 8 + p] * P2s[bsub][p * 8 + r];
    }
    g_env[0][b][rs] = Q0s[bsub][s * 8 + r];
    g_env[1][b][rs] = e1;
    g_env[2][b][rs] = e2;
    g_env[3][b][rs] = P3s[bsub][s * 8 + r];
}

// ---------------------------------------------------------------------------
// Kernel 4: f16 mma.m16n8k16 GEMM (fp32 accum), cp.async double-buffered.
// CTA 128(M) x 128(N), 8 warps as 4Mx2N, warp tile 32x64 (mf=2, nf=8).
// 256 stages: r=st>>5, xq=st&31; stage K = 16 x * 8 s = 8 k16 blocks.
// B frag = one LDS.64 from interleaved g_Gh; A = env*x (fp32 mul, one rn
// pack to f16x2), amortized over 16 MMAs.
// ---------------------------------------------------------------------------
__device__ __forceinline__ void mma16(float* d, const uint32_t* a, const uint32_t* b)
{
    asm volatile(
        "mma.sync.aligned.m16n8k16.row.col.f32.f16.f16.f32 "
        "{%0,%1,%2,%3}, {%4,%5,%6,%7}, {%8,%9}, {%0,%1,%2,%3};\n"
        : "+f"(d[0]), "+f"(d[1]), "+f"(d[2]), "+f"(d[3])
        : "r"(a[0]), "r"(a[1]), "r"(a[2]), "r"(a[3]), "r"(b[0]), "r"(b[1]));
}
__device__ __forceinline__ uint32_t smem_u32(const void* p)
{
    uint32_t a;
    asm("{ .reg .u64 t; cvta.to.shared.u64 t, %1; cvt.u32.u64 %0, t; }" : "=r"(a) : "l"(p));
    return a;
}
__device__ __forceinline__ uint32_t pack_h2(float lo, float hi)
{
    __half2 h = __floats2half2_rn(lo, hi);
    return *(uint32_t*)&h;
}
#define CP_ASYNC16(dst, src) \
    asm volatile("cp.async.cg.shared.global [%0], [%1], 16;" :: "r"(dst), "l"(src))
#define CP_COMMIT() asm volatile("cp.async.commit_group;" ::: "memory")
#define CP_WAIT0()  asm volatile("cp.async.wait_group 0;" ::: "memory")

#define NSTAGE   256
#define ENV_LD   66                    // floats per env row
#define XW       20                    // floats per x row (16 data + 4 pad)
#define BROW     288                   // bytes per B o-row (256 data + 32 pad); 8g+2tg distinct mod 32
#define OFF_ENV  0
#define OFF_X    (128 * ENV_LD * 4)    // 33792
#define XBUF     (128 * XW * 4)        // 10240
#define OFF_B    (OFF_X + 2 * XBUF)    // 54272
#define BBUF     (128 * BROW)          // 36864
#define SMEM_BYTES (OFF_B + 2 * BBUF)  // 128000

__global__ void __launch_bounds__(256, 1) k_gemm(
    const float* __restrict__ X,
    const float* __restrict__ bias, float* __restrict__ out)
{
    extern __shared__ char smc[];
    float* s_env = (float*)(smc + OFF_ENV);
    const uint32_t u_x = smem_u32(smc + OFF_X);
    const uint32_t u_B = smem_u32(smc + OFF_B);

    const int core = blockIdx.z;
    const int m0 = blockIdx.y * 128;
    const int n0 = blockIdx.x * 128;

    const int tid  = threadIdx.x;
    const int lane = tid & 31, warp = tid >> 5;
    const int wm = warp & 3, wn = warp >> 2;          // 4 M-warps x 2 N-warps
    const int g = lane >> 2, tg = lane & 3;
    const int row0 = wm * 32 + g;
    const int nwb  = wn * 64;

    const __half* GhBase = g_Gh + (size_t)(core * 8) * 512 * 4096;

    // issue cp.async for stage st into buffer st&1
    auto stage_async = [&](int st) {
        const int q = st & 1, r = st >> 5, xq = st & 31;
        const __half* src = GhBase + ((size_t)r * 512 + n0) * 4096 + xq * 128;
#pragma unroll
        for (int i = 0; i < 8; i++) {                 // 128 rows x 16 groups
            int idx = tid + i * 256;
            int o = idx >> 4, c = idx & 15;
            CP_ASYNC16(u_B + (uint32_t)(q * BBUF + o * BROW + c * 16),
                       src + (size_t)o * 4096 + c * 8);
        }
        const float* xsrc = X + (size_t)m0 * DIN + core * 512 + xq * 16;
#pragma unroll
        for (int i = 0; i < 2; i++) {                 // 128 rows x 4 float4
            int idx = tid + i * 256;
            int row = idx >> 2, c = idx & 3;
            CP_ASYNC16(u_x + (uint32_t)(q * XBUF + row * (XW * 4) + c * 16),
                       xsrc + (size_t)row * DIN + c * 4);
        }
        CP_COMMIT();
    };

    // stage env tile [128][64]
#pragma unroll
    for (int it = 0; it < 32; it++) {
        int i = tid + it * 256;
        int rr = i >> 6, cc = i & 63;
        s_env[rr * ENV_LD + cc] = g_env[core][m0 + rr][cc];
    }
    stage_async(0);

    float acc[2][8][4];
#pragma unroll
    for (int mf = 0; mf < 2; mf++)
#pragma unroll
        for (int nf = 0; nf < 8; nf++)
#pragma unroll
            for (int q = 0; q < 4; q++) acc[mf][nf][q] = 0.f;

    float2 e0[2], e1[2];

    for (int st = 0; st < NSTAGE; st++) {
        const int q = st & 1, r = st >> 5;
        CP_WAIT0();
        __syncthreads();                  // stage st visible; prev MMAs done
        if (st + 1 < NSTAGE) stage_async(st + 1);

        if ((st & 31) == 0) {             // env pairs for this r
#pragma unroll
            for (int mf = 0; mf < 2; mf++) {
                int rw = row0 + mf * 16;
                e0[mf] = *(const float2*)(s_env + rw * ENV_LD + r * 8 + 2 * tg);
                e1[mf] = *(const float2*)(s_env + (rw + 8) * ENV_LD + r * 8 + 2 * tg);
            }
        }

        const char*  Bq = smc + OFF_B + q * BBUF;
        const float* xb = (const float*)(smc + OFF_X + q * XBUF);

#pragma unroll
        for (int j = 0; j < 8; j++) {     // 8 k16 blocks (x pair j)
            uint2 bf[8];
#pragma unroll
            for (int nf = 0; nf < 8; nf++) {
                int o = nwb + nf * 8 + g;
                bf[nf] = *(const uint2*)(Bq + o * BROW + j * 32 + tg * 8);
            }
            uint32_t af[2][4];
#pragma unroll
            for (int mf = 0; mf < 2; mf++) {
                int rw = row0 + mf * 16;
                float2 xA = *(const float2*)(xb + rw * XW + 2 * j);
                float2 xB = *(const float2*)(xb + (rw + 8) * XW + 2 * j);
                af[mf][0] = pack_h2(e0[mf].x * xA.x, e0[mf].y * xA.x);
                af[mf][1] = pack_h2(e1[mf].x * xB.x, e1[mf].y * xB.x);
                af[mf][2] = pack_h2(e0[mf].x * xA.y, e0[mf].y * xA.y);
                af[mf][3] = pack_h2(e1[mf].x * xB.y, e1[mf].y * xB.y);
            }
#pragma unroll
            for (int mf = 0; mf < 2; mf++)
#pragma unroll
                for (int nf = 0; nf < 8; nf++)
                    mma16(acc[mf][nf], af[mf], (const uint32_t*)&bf[nf]);
        }
    }

    // Epilogue: c0:(g,2tg) c1:(g,2tg+1) c2:(g+8,2tg) c3:(g+8,2tg+1)
#pragma unroll
    for (int mf = 0; mf < 2; mf++) {
        int row = m0 + row0 + mf * 16;
#pragma unroll
        for (int nf = 0; nf < 8; nf++) {
            int col = core * 512 + n0 + nwb + nf * 8 + 2 * tg;
            out[(size_t)row * DOUT + col]           = acc[mf][nf][0] + bias[col];
            out[(size_t)row * DOUT + col + 1]       = acc[mf][nf][1] + bias[col + 1];
            out[(size_t)(row + 8) * DOUT + col]     = acc[mf][nf][2] + bias[col];
            out[(size_t)(row + 8) * DOUT + col + 1] = acc[mf][nf][3] + bias[col + 1];
        }
    }
}

// ---------------------------------------------------------------------------
extern "C" void kernel_launch(void* const* d_in, const int* in_sizes, int n_in,
                              void* d_out, int out_size)
{
    const float* X    = (const float*)d_in[0];
    const float* c0   = (const float*)d_in[1];
    const float* c1   = (const float*)d_in[2];
    const float* c2   = (const float*)d_in[3];
    const float* c3   = (const float*)d_in[4];
    const float* bias = (const float*)d_in[5];
    float* out = (float*)d_out;

    k_zero<<<512, 256>>>();
    k_prep<<<512, 256>>>(c0, c1, c2, c3);
    k_S<<<1024, 256>>>(X);
    k_chain<<<1024, 256>>>();

    cudaFuncSetAttribute(k_gemm, cudaFuncAttributeMaxDynamicSharedMemorySize, SMEM_BYTES);
    dim3 grid(4, 32, 4);   // N-tiles x M-tiles x cores
    k_gemm<<<grid, 256, SMEM_BYTES>>>(X, bias, out);
}

// round 16
// speedup vs baseline: 1.0518x; 1.0518x over previous
#include <cuda_runtime.h>
#include <cuda_fp16.h>
#include <cstdint>

#define B_TOT 4096
#define DIN   2048
#define DOUT  2048
// per core: G[r=8][o=512][x=512][s=8], offset = r*2097152 + o*4096 + x*8 + s

__device__ float g_Ghat[4][8][4096];
__device__ float g_S[4][B_TOT][64];
__device__ float g_env[4][B_TOT][64];
// fp16 copy of G, fragment-interleaved:
// g_Gh[((core*8+r)*512+o)*4096 + grp*16 + p], grp = 16-float group in row,
// p = (s>>1)*4 + (x&1)*2 + (s&1)  -> thread tg reads halfs p=4tg..4tg+3
__device__ __half g_Gh[4u * 8u * 512u * 4096u];

// ---------------------------------------------------------------------------
// Kernel 0: zero g_Ghat (k_prep accumulates via atomicAdd)
// ---------------------------------------------------------------------------
__global__ void k_zero()
{
    ((float*)g_Ghat)[blockIdx.x * 256 + threadIdx.x] = 0.f;   // grid 512
}

// ---------------------------------------------------------------------------
// Kernel 1 (fused): convert G -> fp16 interleaved AND reduce Ghat over o.
// grid 512 = core(4) x r(8) x ochunk(16); block 256; thread t owns 16-float
// group t of each row; loops 32 o's, atomicAdd partial Ghat at the end.
// ---------------------------------------------------------------------------
__global__ void k_prep(const float* __restrict__ c0, const float* __restrict__ c1,
                       const float* __restrict__ c2, const float* __restrict__ c3)
{
    int bid = blockIdx.x;
    int oc = bid & 15, r = (bid >> 4) & 7, core = bid >> 7;
    const float* G = (core == 0) ? c0 : (core == 1) ? c1 : (core == 2) ? c2 : c3;
    int t = threadIdx.x;

    const float* src = G + ((size_t)r * 512 + oc * 32) * 4096 + t * 16;
    __half* dst = g_Gh + ((size_t)(core * 8 + r) * 512 + oc * 32) * 4096 + t * 16;

    float acc[16];
#pragma unroll
    for (int i = 0; i < 16; i++) acc[i] = 0.f;

    for (int oi = 0; oi < 32; oi++) {
        float f[16];
        const float4* s4 = (const float4*)(src + (size_t)oi * 4096);
#pragma unroll
        for (int i = 0; i < 4; i++) {
            float4 v = s4[i];
            f[i * 4 + 0] = v.x; f[i * 4 + 1] = v.y; f[i * 4 + 2] = v.z; f[i * 4 + 3] = v.w;
        }
#pragma unroll
        for (int i = 0; i < 16; i++) acc[i] += f[i];
        __half2 h[8];
#pragma unroll
        for (int s2 = 0; s2 < 4; s2++) {
            h[2 * s2]     = __floats2half2_rn(f[2 * s2],     f[2 * s2 + 1]);     // x even
            h[2 * s2 + 1] = __floats2half2_rn(f[8 + 2 * s2], f[8 + 2 * s2 + 1]); // x odd
        }
        uint4* d4 = (uint4*)(dst + (size_t)oi * 4096);
        const uint32_t* hu = (const uint32_t*)h;
        d4[0] = make_uint4(hu[0], hu[1], hu[2], hu[3]);
        d4[1] = make_uint4(hu[4], hu[5], hu[6], hu[7]);
    }
    float* gh = &g_Ghat[core][r][t * 16];
#pragma unroll
    for (int i = 0; i < 16; i++) atomicAdd(gh + i, acc[i]);
}

// ---------------------------------------------------------------------------
// Kernel 2: S[core][b][r,s] = sum_x Ghat[core][r][x,s] * X[b][core*512+x]
// ---------------------------------------------------------------------------
__global__ void k_S(const float* __restrict__ X)
{
    __shared__ float xs[4][DIN];
    int t = threadIdx.x, b0 = blockIdx.x * 4;
#pragma unroll
    for (int it = 0; it < 32; it++) {
        int i = t + it * 256;
        xs[i >> 11][i & 2047] = X[(size_t)(b0 + (i >> 11)) * DIN + (i & 2047)];
    }
    __syncthreads();
    int core = t >> 6, rs = t & 63, r = rs >> 3, s = rs & 7;
    const float* gh = g_Ghat[core][r];
    const int xo = core * 512;
    float a0 = 0.f, a1 = 0.f, a2 = 0.f, a3 = 0.f;
#pragma unroll 8
    for (int x = 0; x < 512; x++) {
        float ghv = gh[x * 8 + s];
        a0 += ghv * xs[0][xo + x];
        a1 += ghv * xs[1][xo + x];
        a2 += ghv * xs[2][xo + x];
        a3 += ghv * xs[3][xo + x];
    }
    g_S[core][b0 + 0][rs] = a0;
    g_S[core][b0 + 1][rs] = a1;
    g_S[core][b0 + 2][rs] = a2;
    g_S[core][b0 + 3][rs] = a3;
}

// ---------------------------------------------------------------------------
// Kernel 3: chain products -> env
// ---------------------------------------------------------------------------
__global__ void k_chain()
{
    __shared__ float Sm[4][4][64];
    __shared__ float P2s[4][64], P3s[4][64], Q1s[4][64], Q0s[4][64];
    int t = threadIdx.x, bsub = t >> 6, rs = t & 63, r = rs >> 3, s = rs & 7;
    int b = blockIdx.x * 4 + bsub;
#pragma unroll
    for (int c = 0; c < 4; c++) Sm[bsub][c][rs] = g_S[c][b][rs];
    __syncthreads();
    float p2 = 0.f, q1 = 0.f;
#pragma unroll
    for (int p = 0; p < 8; p++) {
        p2 += Sm[bsub][0][r * 8 + p] * Sm[bsub][1][p * 8 + s];
        q1 += Sm[bsub][2][r * 8 + p] * Sm[bsub][3][p * 8 + s];
    }
    P2s[bsub][rs] = p2; Q1s[bsub][rs] = q1;
    __syncthreads();
    float p3 = 0.f, q0 = 0.f;
#pragma unroll
    for (int p = 0; p < 8; p++) {
        p3 += P2s[bsub][r * 8 + p] * Sm[bsub][2][p * 8 + s];
        q0 += Sm[bsub][1][r * 8 + p] * Q1s[bsub][p * 8 + s];
    }
    P3s[bsub][rs] = p3; Q0s[bsub][rs] = q0;
    __syncthreads();
    float e1 = 0.f, e2 = 0.f;
#pragma unroll
    for (int p = 0; p < 8; p++) {
        e1 += Q1s[bsub][s * 8 + p] * Sm[bsub][0][p * 8 + r];
        e2 += Sm[bsub][3][s * 8 + p] * P2s[bsub][p * 8 + r];
    }
    g_env[0][b][rs] = Q0s[bsub][s * 8 + r];
    g_env[1][b][rs] = e1;
    g_env[2][b][rs] = e2;
    g_env[3][b][rs] = P3s[bsub][s * 8 + r];
}

// ---------------------------------------------------------------------------
// Kernel 4: f16 mma.m16n8k16 GEMM (fp32 accum), cp.async double-buffered.
// R10 config (best measured): CTA 128(M) x 64(N), 8 warps 4Mx2N, warp 32x32,
// occupancy 2. 256 stages: r=st>>5, xq=st&31; stage K = 16 x * 8 s = 8 k16.
// B frag = one LDS.64 from interleaved g_Gh; A = env*x (fp32 mul, one rn
// pack to f16x2).
// ---------------------------------------------------------------------------
__device__ __forceinline__ void mma16(float* d, const uint32_t* a, const uint32_t* b)
{
    asm volatile(
        "mma.sync.aligned.m16n8k16.row.col.f32.f16.f16.f32 "
        "{%0,%1,%2,%3}, {%4,%5,%6,%7}, {%8,%9}, {%0,%1,%2,%3};\n"
        : "+f"(d[0]), "+f"(d[1]), "+f"(d[2]), "+f"(d[3])
        : "r"(a[0]), "r"(a[1]), "r"(a[2]), "r"(a[3]), "r"(b[0]), "r"(b[1]));
}
__device__ __forceinline__ uint32_t smem_u32(const void* p)
{
    uint32_t a;
    asm("{ .reg .u64 t; cvta.to.shared.u64 t, %1; cvt.u32.u64 %0, t; }" : "=r"(a) : "l"(p));
    return a;
}
__device__ __forceinline__ uint32_t pack_h2(float lo, float hi)
{
    __half2 h = __floats2half2_rn(lo, hi);
    return *(uint32_t*)&h;
}
#define CP_ASYNC16(dst, src) \
    asm volatile("cp.async.cg.shared.global [%0], [%1], 16;" :: "r"(dst), "l"(src))
#define CP_COMMIT() asm volatile("cp.async.commit_group;" ::: "memory")
#define CP_WAIT0()  asm volatile("cp.async.wait_group 0;" ::: "memory")

#define NSTAGE   256
#define ENV_LD   66                    // floats per env row
#define XW       20                    // floats per x row (16 data + 4 pad)
#define BROW     288                   // bytes per B o-row (256 data + 32 pad)
#define OFF_ENV  0
#define OFF_X    (128 * ENV_LD * 4)    // 33792
#define XBUF     (128 * XW * 4)        // 10240
#define OFF_B    (OFF_X + 2 * XBUF)    // 54272
#define BBUF     (64 * BROW)           // 18432
#define SMEM_BYTES (OFF_B + 2 * BBUF)  // 91136

__global__ void __launch_bounds__(256, 2) k_gemm(
    const float* __restrict__ X,
    const float* __restrict__ bias, float* __restrict__ out)
{
    extern __shared__ char smc[];
    float* s_env = (float*)(smc + OFF_ENV);
    const uint32_t u_x = smem_u32(smc + OFF_X);
    const uint32_t u_B = smem_u32(smc + OFF_B);

    const int core = blockIdx.z;
    const int m0 = blockIdx.y * 128;
    const int n0 = blockIdx.x * 64;

    const int tid  = threadIdx.x;
    const int lane = tid & 31, warp = tid >> 5;
    const int wm = warp & 3, wn = warp >> 2;          // 4 M-warps x 2 N-warps
    const int g = lane >> 2, tg = lane & 3;
    const int row0 = wm * 32 + g;

    const __half* GhBase = g_Gh + (size_t)(core * 8) * 512 * 4096;

    // issue cp.async for stage st into buffer st&1
    auto stage_async = [&](int st) {
        const int q = st & 1, r = st >> 5, xq = st & 31;
        const __half* src = GhBase + ((size_t)r * 512 + n0) * 4096 + xq * 128;
#pragma unroll
        for (int i = 0; i < 4; i++) {                 // 64 rows x 16 groups
            int idx = tid + i * 256;
            int o = idx >> 4, c = idx & 15;
            CP_ASYNC16(u_B + (uint32_t)(q * BBUF + o * BROW + c * 16),
                       src + (size_t)o * 4096 + c * 8);
        }
        const float* xsrc = X + (size_t)m0 * DIN + core * 512 + xq * 16;
#pragma unroll
        for (int i = 0; i < 2; i++) {                 // 128 rows x 4 float4
            int idx = tid + i * 256;
            int row = idx >> 2, c = idx & 3;
            CP_ASYNC16(u_x + (uint32_t)(q * XBUF + row * (XW * 4) + c * 16),
                       xsrc + (size_t)row * DIN + c * 4);
        }
        CP_COMMIT();
    };

    // stage env tile [128][64]
#pragma unroll
    for (int it = 0; it < 32; it++) {
        int i = tid + it * 256;
        int rr = i >> 6, cc = i & 63;
        s_env[rr * ENV_LD + cc] = g_env[core][m0 + rr][cc];
    }
    stage_async(0);

    float acc[2][4][4];
#pragma unroll
    for (int mf = 0; mf < 2; mf++)
#pragma unroll
        for (int nf = 0; nf < 4; nf++)
#pragma unroll
            for (int q = 0; q < 4; q++) acc[mf][nf][q] = 0.f;

    float2 e0[2], e1[2];

    for (int st = 0; st < NSTAGE; st++) {
        const int q = st & 1, r = st >> 5;
        CP_WAIT0();
        __syncthreads();                  // stage st visible; prev MMAs done
        if (st + 1 < NSTAGE) stage_async(st + 1);

        if ((st & 31) == 0) {             // env pairs for this r
#pragma unroll
            for (int mf = 0; mf < 2; mf++) {
                int rw = row0 + mf * 16;
                e0[mf] = *(const float2*)(s_env + rw * ENV_LD + r * 8 + 2 * tg);
                e1[mf] = *(const float2*)(s_env + (rw + 8) * ENV_LD + r * 8 + 2 * tg);
            }
        }

        const char*  Bq = smc + OFF_B + q * BBUF;
        const float* xb = (const float*)(smc + OFF_X + q * XBUF);

#pragma unroll
        for (int j = 0; j < 8; j++) {     // 8 k16 blocks (x pair j)
            uint2 bf[4];
#pragma unroll
            for (int nf = 0; nf < 4; nf++) {
                int o = wn * 32 + nf * 8 + g;
                bf[nf] = *(const uint2*)(Bq + o * BROW + j * 32 + tg * 8);
            }
            uint32_t af[2][4];
#pragma unroll
            for (int mf = 0; mf < 2; mf++) {
                int rw = row0 + mf * 16;
                float2 xA = *(const float2*)(xb + rw * XW + 2 * j);
                float2 xB = *(const float2*)(xb + (rw + 8) * XW + 2 * j);
                af[mf][0] = pack_h2(e0[mf].x * xA.x, e0[mf].y * xA.x);
                af[mf][1] = pack_h2(e1[mf].x * xB.x, e1[mf].y * xB.x);
                af[mf][2] = pack_h2(e0[mf].x * xA.y, e0[mf].y * xA.y);
                af[mf][3] = pack_h2(e1[mf].x * xB.y, e1[mf].y * xB.y);
            }
#pragma unroll
            for (int mf = 0; mf < 2; mf++)
#pragma unroll
                for (int nf = 0; nf < 4; nf++)
                    mma16(acc[mf][nf], af[mf], (const uint32_t*)&bf[nf]);
        }
    }

    // Epilogue: c0:(g,2tg) c1:(g,2tg+1) c2:(g+8,2tg) c3:(g+8,2tg+1)
#pragma unroll
    for (int mf = 0; mf < 2; mf++) {
        int row = m0 + row0 + mf * 16;
#pragma unroll
        for (int nf = 0; nf < 4; nf++) {
            int col = core * 512 + n0 + wn * 32 + nf * 8 + 2 * tg;
            out[(size_t)row * DOUT + col]           = acc[mf][nf][0] + bias[col];
            out[(size_t)row * DOUT + col + 1]       = acc[mf][nf][1] + bias[col + 1];
            out[(size_t)(row + 8) * DOUT + col]     = acc[mf][nf][2] + bias[col];
            out[(size_t)(row + 8) * DOUT + col + 1] = acc[mf][nf][3] + bias[col + 1];
        }
    }
}

// ---------------------------------------------------------------------------
extern "C" void kernel_launch(void* const* d_in, const int* in_sizes, int n_in,
                              void* d_out, int out_size)
{
    const float* X    = (const float*)d_in[0];
    const float* c0   = (const float*)d_in[1];
    const float* c1   = (const float*)d_in[2];
    const float* c2   = (const float*)d_in[3];
    const float* c3   = (const float*)d_in[4];
    const float* bias = (const float*)d_in[5];
    float* out = (float*)d_out;

    k_zero<<<512, 256>>>();
    k_prep<<<512, 256>>>(c0, c1, c2, c3);
    k_S<<<1024, 256>>>(X);
    k_chain<<<1024, 256>>>();

    cudaFuncSetAttribute(k_gemm, cudaFuncAttributeMaxDynamicSharedMemorySize, SMEM_BYTES);
    dim3 grid(8, 32, 4);   // N-tiles x M-tiles x cores
    k_gemm<<<grid, 256, SMEM_BYTES>>>(X, bias, out);
}